// round 1
// baseline (speedup 1.0000x reference)
#include <cuda_runtime.h>

// MoE gating for x:[4,4096,1024] f32, gate_w:[64,1024] f32.
// Outputs (concatenated f32): top_scores [T,2], top_idx [T,2] (as float), total_loss [1].
// T = 16384, E = 64, H = 1024.

#define H      1024
#define NE     64
#define KC     32
#define TM     128
#define NT     256
#define XS_STR (TM + 2)      // 130: odd*2 stride -> conflict-free transpose stores, LDS.64-aligned
#define WS_STR (2 * NE + 2)  // 130: duplicated (w,w) pairs
#define SP_STR (NE + 1)      // 65
#define MAXBLK 256

// Deterministic per-block partials for the loss (no float atomics).
__device__ float g_pexp[MAXBLK * NE];
__device__ float g_pz2[MAXBLK];

__device__ __forceinline__ void fma_f32x2(unsigned long long& d,
                                          unsigned long long a,
                                          unsigned long long b) {
    asm("fma.rn.f32x2 %0, %1, %2, %0;" : "+l"(d) : "l"(a), "l"(b));
}

__global__ __launch_bounds__(NT) void moe_gate(const float* __restrict__ x,
                                               const float* __restrict__ w,
                                               float* __restrict__ out,
                                               int T) {
    __shared__ __align__(16) float smem[8456];
    float* xs  = smem;                  // [KC][XS_STR]  x chunk, k-major (token pairs contiguous)
    float* ws2 = smem + KC * XS_STR;    // [KC][WS_STR]  w chunk, k-major, each value duplicated

    const int tid  = threadIdx.x;
    const int tBlk = blockIdx.x * TM;

    const int tx = tid & 15;   // expert group: e0..e0+3
    const int ty = tid >> 4;   // token group:  t0..t0+7 (4 packed pairs)
    const int e0 = tx * 4;
    const int t0 = ty * 8;

    unsigned long long acc[4][4];  // [token-pair][expert], f32x2 accumulators
#pragma unroll
    for (int i = 0; i < 4; i++)
#pragma unroll
        for (int j = 0; j < 4; j++) acc[i][j] = 0ull;

    // cooperative-load index maps
    const int xTok = tid >> 3;        // 0..31
    const int xK   = (tid & 7) * 4;   // 0..28
    const int wE   = tid >> 2;        // 0..63
    const int wK   = (tid & 3) * 8;   // 0,8,16,24

    for (int kc = 0; kc < H; kc += KC) {
        __syncthreads();
        // x chunk: 128 tokens x 32 k, coalesced float4 along k, transposed scalar stores
#pragma unroll
        for (int p = 0; p < 4; p++) {
            int t = p * 32 + xTok;
            float4 v = *(const float4*)(x + (size_t)(tBlk + t) * H + kc + xK);
            xs[(xK + 0) * XS_STR + t] = v.x;
            xs[(xK + 1) * XS_STR + t] = v.y;
            xs[(xK + 2) * XS_STR + t] = v.z;
            xs[(xK + 3) * XS_STR + t] = v.w;
        }
        // w chunk: 64 e x 32 k, duplicated pairs so compute loads are LDS.64 (no packing)
#pragma unroll
        for (int q = 0; q < 2; q++) {
            int k = wK + q * 4;
            float4 v = *(const float4*)(w + (size_t)wE * H + kc + k);
            ws2[(k + 0) * WS_STR + 2 * wE]     = v.x;
            ws2[(k + 0) * WS_STR + 2 * wE + 1] = v.x;
            ws2[(k + 1) * WS_STR + 2 * wE]     = v.y;
            ws2[(k + 1) * WS_STR + 2 * wE + 1] = v.y;
            ws2[(k + 2) * WS_STR + 2 * wE]     = v.z;
            ws2[(k + 2) * WS_STR + 2 * wE + 1] = v.z;
            ws2[(k + 3) * WS_STR + 2 * wE]     = v.w;
            ws2[(k + 3) * WS_STR + 2 * wE + 1] = v.w;
        }
        __syncthreads();
#pragma unroll 8
        for (int k = 0; k < KC; k++) {
            const float* xr = xs  + k * XS_STR + t0;
            const float* wr = ws2 + k * WS_STR + 2 * e0;
            unsigned long long a[4], b[4];
#pragma unroll
            for (int i = 0; i < 4; i++)
                a[i] = *(const unsigned long long*)(xr + 2 * i);
#pragma unroll
            for (int j = 0; j < 4; j++)
                b[j] = *(const unsigned long long*)(wr + 2 * j);
#pragma unroll
            for (int i = 0; i < 4; i++)
#pragma unroll
                for (int j = 0; j < 4; j++)
                    fma_f32x2(acc[i][j], a[i], b[j]);
        }
    }
    __syncthreads();

    // ---- epilogue: reuse smem for logits [TM][SP_STR] ----
    float* sP   = smem;                  // 8320 floats
    float* sInv = smem + TM * SP_STR;    // 128
    float* sRed = sInv + TM;             // 8

#pragma unroll
    for (int i = 0; i < 4; i++)
#pragma unroll
        for (int j = 0; j < 4; j++) {
            float2 f = *(float2*)&acc[i][j];
            sP[(t0 + 2 * i)     * SP_STR + e0 + j] = f.x;
            sP[(t0 + 2 * i + 1) * SP_STR + e0 + j] = f.y;
        }
    __syncthreads();

    float zsq = 0.0f;
    if (tid < TM) {
        float* row = sP + tid * SP_STR;
        float m = row[0];
#pragma unroll 8
        for (int e = 1; e < NE; e++) m = fmaxf(m, row[e]);
        float sum = 0.0f;
        float b1 = -1e30f, b2 = -1e30f;
        int i1 = 0, i2 = 0;
        for (int e = 0; e < NE; e++) {
            float l  = row[e];
            float ex = __expf(l - m);
            sum += ex;
            row[e] = ex;   // keep exp for expert-load pass
            if (l > b1)      { b2 = b1; i2 = i1; b1 = l; i1 = e; }
            else if (l > b2) { b2 = l;  i2 = e; }
        }
        float inv = 1.0f / sum;
        sInv[tid] = inv;
        float z = m + __logf(sum);
        zsq = z * z;
        // renorm softmax over the two *probabilities* (matches reference exactly)
        float p1 = __expf(b1 - m) * inv;
        float p2 = __expf(b2 - m) * inv;
        float d  = __expf(p2 - p1);
        float q1 = 1.0f / (1.0f + d);
        float q2 = d / (1.0f + d);
        int gt = tBlk + tid;
        out[2 * gt]             = q1;
        out[2 * gt + 1]         = q2;
        out[2 * T + 2 * gt]     = (float)i1;
        out[2 * T + 2 * gt + 1] = (float)i2;
    }
    // block z^2 reduction (threads >= TM contribute 0)
#pragma unroll
    for (int off = 16; off > 0; off >>= 1)
        zsq += __shfl_down_sync(0xffffffffu, zsq, off);
    if ((tid & 31) == 0) sRed[tid >> 5] = zsq;
    __syncthreads();
    if (tid == 0) {
        float s = 0.0f;
        for (int wi = 0; wi < NT / 32; wi++) s += sRed[wi];
        g_pz2[blockIdx.x] = s;
    }
    // per-expert score sums (deterministic, conflict-free: bank = (t + e) % 32)
    if (tid < NE) {
        float s = 0.0f;
#pragma unroll 4
        for (int t = 0; t < TM; t++)
            s += sP[t * SP_STR + tid] * sInv[t];
        g_pexp[blockIdx.x * NE + tid] = s;
    }
}

__global__ void moe_finalize(float* __restrict__ out, int nblk, int T) {
    __shared__ float redA[NE];
    __shared__ float redZ[NE];
    int e = threadIdx.x;
    float s = 0.0f;
    for (int b = 0; b < nblk; b++) s += g_pexp[b * NE + e];
    float load = s / (float)T;
    float d = load - 1.0f / 64.0f;
    redA[e] = d * d;
    float z2 = 0.0f;
    for (int b = e; b < nblk; b += NE) z2 += g_pz2[b];
    redZ[e] = z2;
    __syncthreads();
    if (e == 0) {
        float lb = 0.0f, zz = 0.0f;
        for (int i = 0; i < NE; i++) { lb += redA[i]; zz += redZ[i]; }
        out[4 * T] = 0.01f * 64.0f * lb + 1e-4f * (zz / (float)T);
    }
}

extern "C" void kernel_launch(void* const* d_in, const int* in_sizes, int n_in,
                              void* d_out, int out_size) {
    const float* x = (const float*)d_in[0];
    const float* w = (const float*)d_in[1];
    float* out = (float*)d_out;
    int T = in_sizes[0] / H;      // 16384
    int nblk = T / TM;            // 128
    moe_gate<<<nblk, NT>>>(x, w, out, T);
    moe_finalize<<<1, NE>>>(out, nblk, T);
}

// round 2
// speedup vs baseline: 1.4994x; 1.4994x over previous
#include <cuda_runtime.h>

// MoE gating: x:[4,4096,1024] f32, gate_w:[64,1024] f32.
// out (f32): top_scores [T,2] | top_idx [T,2] | total_loss [1]. T=16384.

#define H      1024
#define NE     64
#define KC     16
#define NCHUNK (H / KC)      // 64
#define TM     128
#define NT     256
#define XS_STR 130
#define WS_STR 130
#define BUF    2080          // KC * 130
#define SP_STR 65
#define MAXBLK 256

__device__ float g_pexp[MAXBLK * NE];
__device__ float g_pz2[MAXBLK];

__device__ __forceinline__ void fma_f32x2(unsigned long long& d,
                                          unsigned long long a,
                                          unsigned long long b) {
    asm("fma.rn.f32x2 %0, %1, %2, %0;" : "+l"(d) : "l"(a), "l"(b));
}

__global__ __launch_bounds__(NT) void moe_gate(const float* __restrict__ x,
                                               const float* __restrict__ w,
                                               float* __restrict__ out,
                                               int T) {
    __shared__ __align__(16) float smem[8456];
    // pipeline layout: xs buf0 @0, xs buf1 @2080, ws buf0 @4160, ws buf1 @6240
    // epilogue reuse:  sP @0 (128*65), sInv @8320, sRed @8448

    const int tid  = threadIdx.x;
    const int tBlk = blockIdx.x * TM;

    // compute mapping: thread owns tokens t0..t0+7 (pairs), experts {tx+16j}
    const int tx = tid & 15;
    const int ty = tid >> 4;
    const int t0 = ty * 8;

    unsigned long long acc[4][4];
#pragma unroll
    for (int i = 0; i < 4; i++)
#pragma unroll
        for (int j = 0; j < 4; j++) acc[i][j] = 0ull;

    // global-load mapping
    const int xTok = tid >> 1;          // 0..127
    const int xOff = (tid & 1) * 8;     // 0 or 8
    const int wE   = tid >> 2;          // 0..63
    const int wK   = (tid & 3) * 4;     // 0,4,8,12
    const float* xg = x + (size_t)(tBlk + xTok) * H + xOff;
    const float* wg = w + (size_t)wE * H + wK;

    // ---- prologue: chunk 0 -> regs -> buf 0 ----
    float4 xv0 = *(const float4*)(xg);
    float4 xv1 = *(const float4*)(xg + 4);
    float4 wv  = *(const float4*)(wg);
    {
        float* xs = smem;
        float* ws = smem + 4160;
        xs[(xOff + 0) * XS_STR + xTok] = xv0.x;
        xs[(xOff + 1) * XS_STR + xTok] = xv0.y;
        xs[(xOff + 2) * XS_STR + xTok] = xv0.z;
        xs[(xOff + 3) * XS_STR + xTok] = xv0.w;
        xs[(xOff + 4) * XS_STR + xTok] = xv1.x;
        xs[(xOff + 5) * XS_STR + xTok] = xv1.y;
        xs[(xOff + 6) * XS_STR + xTok] = xv1.z;
        xs[(xOff + 7) * XS_STR + xTok] = xv1.w;
        ws[(wK + 0) * WS_STR + 2 * wE]     = wv.x;
        ws[(wK + 0) * WS_STR + 2 * wE + 1] = wv.x;
        ws[(wK + 1) * WS_STR + 2 * wE]     = wv.y;
        ws[(wK + 1) * WS_STR + 2 * wE + 1] = wv.y;
        ws[(wK + 2) * WS_STR + 2 * wE]     = wv.z;
        ws[(wK + 2) * WS_STR + 2 * wE + 1] = wv.z;
        ws[(wK + 3) * WS_STR + 2 * wE]     = wv.w;
        ws[(wK + 3) * WS_STR + 2 * wE + 1] = wv.w;
    }

    for (int c = 0; c < NCHUNK; c++) {
        __syncthreads();
        // prefetch next chunk into registers (issue before compute)
        if (c < NCHUNK - 1) {
            const float* xp = xg + (c + 1) * KC;
            xv0 = *(const float4*)(xp);
            xv1 = *(const float4*)(xp + 4);
            wv  = *(const float4*)(wg + (c + 1) * KC);
        }
        // compute current buffer
        const float* xs = smem + (c & 1) * BUF;
        const float* ws = smem + 4160 + (c & 1) * BUF;
#pragma unroll
        for (int k = 0; k < KC; k++) {
            const float* xr = xs + k * XS_STR + t0;
            const float* wr = ws + k * WS_STR + 2 * tx;
            unsigned long long a[4], b[4];
#pragma unroll
            for (int i = 0; i < 4; i++)
                a[i] = *(const unsigned long long*)(xr + 2 * i);
#pragma unroll
            for (int j = 0; j < 4; j++)
                b[j] = *(const unsigned long long*)(wr + 32 * j);
#pragma unroll
            for (int i = 0; i < 4; i++)
#pragma unroll
                for (int j = 0; j < 4; j++)
                    fma_f32x2(acc[i][j], a[i], b[j]);
        }
        // stage next chunk into the other buffer
        if (c < NCHUNK - 1) {
            float* xs2 = smem + ((c + 1) & 1) * BUF;
            float* ws2 = smem + 4160 + ((c + 1) & 1) * BUF;
            xs2[(xOff + 0) * XS_STR + xTok] = xv0.x;
            xs2[(xOff + 1) * XS_STR + xTok] = xv0.y;
            xs2[(xOff + 2) * XS_STR + xTok] = xv0.z;
            xs2[(xOff + 3) * XS_STR + xTok] = xv0.w;
            xs2[(xOff + 4) * XS_STR + xTok] = xv1.x;
            xs2[(xOff + 5) * XS_STR + xTok] = xv1.y;
            xs2[(xOff + 6) * XS_STR + xTok] = xv1.z;
            xs2[(xOff + 7) * XS_STR + xTok] = xv1.w;
            ws2[(wK + 0) * WS_STR + 2 * wE]     = wv.x;
            ws2[(wK + 0) * WS_STR + 2 * wE + 1] = wv.x;
            ws2[(wK + 1) * WS_STR + 2 * wE]     = wv.y;
            ws2[(wK + 1) * WS_STR + 2 * wE + 1] = wv.y;
            ws2[(wK + 2) * WS_STR + 2 * wE]     = wv.z;
            ws2[(wK + 2) * WS_STR + 2 * wE + 1] = wv.z;
            ws2[(wK + 3) * WS_STR + 2 * wE]     = wv.w;
            ws2[(wK + 3) * WS_STR + 2 * wE + 1] = wv.w;
        }
    }
    __syncthreads();

    // ---- epilogue: logits -> smem [TM][SP_STR] ----
    float* sP   = smem;
    float* sInv = smem + TM * SP_STR;   // 8320
    float* sRed = sInv + TM;            // 8448

#pragma unroll
    for (int i = 0; i < 4; i++)
#pragma unroll
        for (int j = 0; j < 4; j++) {
            float2 f = *(float2*)&acc[i][j];
            int e = tx + 16 * j;
            sP[(t0 + 2 * i)     * SP_STR + e] = f.x;
            sP[(t0 + 2 * i + 1) * SP_STR + e] = f.y;
        }
    __syncthreads();

    float zsq = 0.0f;
    if (tid < TM) {
        float* row = sP + tid * SP_STR;
        float m = row[0];
#pragma unroll 8
        for (int e = 1; e < NE; e++) m = fmaxf(m, row[e]);
        float sum = 0.0f;
        float b1 = -1e30f, b2 = -1e30f;
        int i1 = 0, i2 = 0;
        for (int e = 0; e < NE; e++) {
            float l  = row[e];
            float ex = __expf(l - m);
            sum += ex;
            row[e] = ex;
            if (l > b1)      { b2 = b1; i2 = i1; b1 = l; i1 = e; }
            else if (l > b2) { b2 = l;  i2 = e; }
        }
        float inv = 1.0f / sum;
        sInv[tid] = inv;
        float z = m + __logf(sum);
        zsq = z * z;
        float p1 = __expf(b1 - m) * inv;
        float p2 = __expf(b2 - m) * inv;
        float d  = __expf(p2 - p1);
        float q1 = 1.0f / (1.0f + d);
        float q2 = d / (1.0f + d);
        int gt = tBlk + tid;
        out[2 * gt]             = q1;
        out[2 * gt + 1]         = q2;
        out[2 * T + 2 * gt]     = (float)i1;
        out[2 * T + 2 * gt + 1] = (float)i2;
    }
#pragma unroll
    for (int off = 16; off > 0; off >>= 1)
        zsq += __shfl_down_sync(0xffffffffu, zsq, off);
    if ((tid & 31) == 0) sRed[tid >> 5] = zsq;
    __syncthreads();
    if (tid == 0) {
        float s = 0.0f;
        for (int wi = 0; wi < NT / 32; wi++) s += sRed[wi];
        g_pz2[blockIdx.x] = s;
    }
    if (tid < NE) {
        float s = 0.0f;
#pragma unroll 4
        for (int t = 0; t < TM; t++)
            s += sP[t * SP_STR + tid] * sInv[t];
        g_pexp[blockIdx.x * NE + tid] = s;
    }
}

__global__ void moe_finalize(float* __restrict__ out, int nblk, int T) {
    __shared__ float redA[4][NE];
    __shared__ float redZ[256];
    const int tid  = threadIdx.x;
    const int e    = tid & 63;
    const int part = tid >> 6;
    float s = 0.0f;
#pragma unroll 4
    for (int b = part; b < nblk; b += 4) s += g_pexp[b * NE + e];
    redA[part][e] = s;
    float z2 = 0.0f;
    for (int b = tid; b < nblk; b += 256) z2 += g_pz2[b];
    redZ[tid] = z2;
    __syncthreads();
    if (tid < 32) {
        float lb = 0.0f;
#pragma unroll
        for (int i = tid; i < NE; i += 32) {
            float load = (redA[0][i] + redA[1][i] + redA[2][i] + redA[3][i]) / (float)T;
            float d = load - 1.0f / 64.0f;
            lb += d * d;
        }
        float zz = redZ[tid] + redZ[tid + 32] + redZ[tid + 64] + redZ[tid + 96] +
                   redZ[tid + 128] + redZ[tid + 160] + redZ[tid + 192] + redZ[tid + 224];
#pragma unroll
        for (int off = 16; off > 0; off >>= 1) {
            lb += __shfl_down_sync(0xffffffffu, lb, off);
            zz += __shfl_down_sync(0xffffffffu, zz, off);
        }
        if (tid == 0)
            out[4 * T] = 0.01f * 64.0f * lb + 1e-4f * (zz / (float)T);
    }
}

extern "C" void kernel_launch(void* const* d_in, const int* in_sizes, int n_in,
                              void* d_out, int out_size) {
    const float* x = (const float*)d_in[0];
    const float* w = (const float*)d_in[1];
    float* out = (float*)d_out;
    int T = in_sizes[0] / H;   // 16384
    int nblk = T / TM;         // 128
    moe_gate<<<nblk, NT>>>(x, w, out, T);
    moe_finalize<<<1, 256>>>(out, nblk, T);
}